// round 5
// baseline (speedup 1.0000x reference)
#include <cuda_runtime.h>
#include <cstdint>

#define NN     512
#define FIN    256
#define HF     256
#define NH     8
#define NF     32
#define NB     4
#define ITILE  32    // i-rows per CTA
#define GLS    36    // gl/gr smem row stride (floats): 16B-aligned, LDS.128 conflict-free
#define GRS    36
#define ATS    34    // p-matrix [j][i_local] stride (floats), 8B-aligned pairs

typedef unsigned long long ull;

__device__ float g_scratch[(size_t)NB * NN * 512];

// ---- packed f32x2 helpers -------------------------------------------------
__device__ __forceinline__ ull pack2(float lo, float hi) {
    ull r; asm("mov.b64 %0, {%1, %2};" : "=l"(r) : "f"(lo), "f"(hi)); return r;
}
__device__ __forceinline__ void unpack2(ull v, float& lo, float& hi) {
    asm("mov.b64 {%0, %1}, %2;" : "=f"(lo), "=f"(hi) : "l"(v));
}
__device__ __forceinline__ ull add2(ull a, ull b) {
    ull r; asm("add.rn.f32x2 %0, %1, %2;" : "=l"(r) : "l"(a), "l"(b)); return r;
}
__device__ __forceinline__ ull fma2(ull a, ull b, ull c) {
    ull r; asm("fma.rn.f32x2 %0, %1, %2, %3;" : "=l"(r) : "l"(a), "l"(b), "l"(c)); return r;
}
#define ABS2 0x7FFFFFFF7FFFFFFFULL

// ---------------------------------------------------------------------------
// Kernel 1: fused GEMM  g_l = h @ W_l, g_r = h @ W_r  (double-buffered smem)
// ---------------------------------------------------------------------------
__global__ __launch_bounds__(256, 2)
void gemm_kernel(const float* __restrict__ A,
                 const float* __restrict__ WL,
                 const float* __restrict__ WR) {
    __shared__ float As[2][16][64];
    __shared__ float Bs[2][16][68];

    const int nb = blockIdx.x;
    const float* Bm = (nb < 4) ? WL : WR;
    const int colOff = (nb < 4) ? 0 : 256;
    const int n0 = (nb & 3) * 64;
    const int m0 = blockIdx.y * 64;

    const int tid = threadIdx.x;
    const int tx = tid & 15;
    const int ty = tid >> 4;

    const int arow = tid >> 2;
    const int acol = (tid & 3) << 2;
    const int brow = tid >> 4;
    const int bcol = (tid & 15) << 2;

    const float* Aptr = A  + (size_t)(m0 + arow) * FIN + acol;
    const float* Bptr = Bm + (size_t)brow * HF + n0 + bcol;

    ull cc[4][2] = {};

    float4 av = *(const float4*)Aptr;
    float4 bv = *(const float4*)Bptr;

#pragma unroll 1
    for (int s = 0; s < 16; s++) {
        const int buf = s & 1;
        As[buf][acol + 0][arow] = av.x;
        As[buf][acol + 1][arow] = av.y;
        As[buf][acol + 2][arow] = av.z;
        As[buf][acol + 3][arow] = av.w;
        *(float4*)&Bs[buf][brow][bcol] = bv;
        __syncthreads();
        if (s < 15) {
            av = *(const float4*)(Aptr + (s + 1) * 16);
            bv = *(const float4*)(Bptr + (size_t)(s + 1) * 16 * HF);
        }
#pragma unroll
        for (int k = 0; k < 16; k++) {
            const ulonglong2 b2 = *(const ulonglong2*)&Bs[buf][k][tx * 4];
#pragma unroll
            for (int r = 0; r < 4; r++) {
                const float a = As[buf][k][ty * 4 + r];
                const ull pa = pack2(a, a);
                cc[r][0] = fma2(pa, b2.x, cc[r][0]);
                cc[r][1] = fma2(pa, b2.y, cc[r][1]);
            }
        }
    }

    float* C = g_scratch + (size_t)m0 * 512 + colOff + n0;
#pragma unroll
    for (int r = 0; r < 4; r++) {
        ulonglong2 v; v.x = cc[r][0]; v.y = cc[r][1];
        *(ulonglong2*)(C + (size_t)(ty * 4 + r) * 512 + tx * 4) = v;
    }
}

// ---------------------------------------------------------------------------
// Kernel 2: fused GATv2 attention. CTA = (b, h, 32 i-rows), 512 threads,
// 16 warps x 2 i-rows. wb2 in smem (broadcast), gri in regs (64).
// e[i,j] = Sl[j] + Sr[i] + sum_f wb_f|gl[j,f]+gr[i,f]|; p = exp(e) or 0.
// ---------------------------------------------------------------------------
#define OFF_GL   0
#define OFF_GR   (NN * GLS)                    // 18432
#define OFF_AT   (OFF_GR + NN * GRS)           // 36864
#define OFF_SL   (OFF_AT + NN * ATS)           // 54272
#define OFF_SR   (OFF_SL + NN)                 // 54784
#define OFF_SINV (OFF_SR + ITILE)              // 54816
#define OFF_WB   (OFF_SINV + ITILE)            // 54848 (16B aligned)
#define OFF_MASK (OFF_WB + 32)                 // 54880
#define SMEM_FLOATS (OFF_MASK + ITILE * 16)    // 55392
#define SMEM_BYTES  (SMEM_FLOATS * 4)          // 221568

__global__ __launch_bounds__(512, 1)
void attn_kernel(const int* __restrict__ adj,
                 const float* __restrict__ attn_w,
                 float* __restrict__ out) {
    extern __shared__ float sm[];
    float* gl_s  = sm + OFF_GL;
    float* gr_s  = sm + OFF_GR;
    float* at_s  = sm + OFF_AT;     // p[j][i_local], stride 34
    float* Sl_s  = sm + OFF_SL;
    float* Sr_s  = sm + OFF_SR;
    float* sinv  = sm + OFF_SINV;
    ull*   wb_s  = (ull*)(sm + OFF_WB);             // 16 packed wb pairs
    unsigned* mask_s = (unsigned*)(sm + OFF_MASK);  // [32 rows][16 words]

    const int b  = blockIdx.z;
    const int h  = blockIdx.y;
    const int i0 = blockIdx.x * ITILE;
    const int tid  = threadIdx.x;
    const int lane = tid & 31;
    const int warp = tid >> 5;      // 0..15

    // ---- stage g_l / g_r slices into smem ----
    const float* gbase = g_scratch + ((size_t)b * NN) * 512 + h * NF;
#pragma unroll
    for (int it = 0; it < 8; it++) {
        const int idx = it * 512 + tid;            // 0..4095
        const int j = idx >> 3;
        const int q = (idx & 7) << 2;
        const float* gp = gbase + (size_t)j * 512 + q;
        const float4 v = *(const float4*)gp;
        const float4 u = *(const float4*)(gp + 256);
        *(float4*)(gl_s + j * GLS + q) = v;
        *(float4*)(gr_s + j * GRS + q) = u;
    }

    // ---- adj -> bitmask: one 32-bit word per thread ----
    {
        const int row = tid >> 4;                  // 0..31
        const int chunk = tid & 15;                // 0..15
        const int4* ap = (const int4*)(adj + (size_t)(i0 + row) * NN + chunk * 32);
        unsigned w = 0;
#pragma unroll
        for (int k = 0; k < 8; k++) {
            const int4 v = ap[k];
            unsigned nib = (v.x != 0) | ((v.y != 0) << 1) |
                           ((v.z != 0) << 2) | ((v.w != 0) << 3);
            w |= nib << (4 * k);
        }
        mask_s[tid] = w;
    }

    // ---- packed wb into smem (wb = 0.395 w) ----
    if (tid < 16) {
        const float w0 = __ldg(attn_w + 2 * tid);
        const float w1 = __ldg(attn_w + 2 * tid + 1);
        wb_s[tid] = pack2(0.395f * w0, 0.395f * w1);
    }
    __syncthreads();

    // ---- Sl[j] (one per thread), Sr[i] (32 rows) ----
    {
        const int j = tid;
        const ull* glp = (const ull*)(gl_s + j * GLS);
        ull acc = 0;
#pragma unroll
        for (int p = 0; p < 16; p++) acc = fma2(wb_s[p], glp[p], acc);
        float lo, hi; unpack2(acc, lo, hi);
        Sl_s[j] = 1.5316455696f * (lo + hi);       // *(0.605/0.395)
    }
    if (tid < ITILE) {
        const ull* grp = (const ull*)(gr_s + (i0 + tid) * GRS);
        ull acc = 0;
#pragma unroll
        for (int p = 0; p < 16; p++) acc = fma2(wb_s[p], grp[p], acc);
        float lo, hi; unpack2(acc, lo, hi);
        Sr_s[tid] = 1.5316455696f * (lo + hi);
    }
    __syncthreads();

    // ---- pass 1: scores + mask + exp + row-sum (warp w: rows 2w, 2w+1) ----
    {
        const int r0 = warp * 2;
        ull gri0[16], gri1[16];
        {
            const ull* ga = (const ull*)(gr_s + (i0 + r0) * GRS);
            const ull* gb = (const ull*)(gr_s + (i0 + r0 + 1) * GRS);
#pragma unroll
            for (int p = 0; p < 16; p++) { gri0[p] = ga[p]; gri1[p] = gb[p]; }
        }
        const float Sr0 = Sr_s[r0];
        const float Sr1 = Sr_s[r0 + 1];
        const unsigned* mrow0 = mask_s + (r0) * 16;
        const unsigned* mrow1 = mask_s + (r0 + 1) * 16;
        const ulonglong2* wbp2 = (const ulonglong2*)wb_s;
        float sum0 = 0.f, sum1 = 0.f;

#pragma unroll 2
        for (int jj = 0; jj < 16; jj++) {
            const int j = (jj << 5) + lane;
            const ulonglong2* glp = (const ulonglong2*)(gl_s + j * GLS);
            const unsigned mw0 = (mrow0[jj] >> lane) & 1;
            const unsigned mw1 = (mrow1[jj] >> lane) & 1;
            const float slj = Sl_s[j];
            ull a00 = 0, a01 = 0, a10 = 0, a11 = 0;
#pragma unroll
            for (int q = 0; q < 8; q++) {
                const ulonglong2 gv = glp[q];
                const ulonglong2 wv = wbp2[q];
                const int p0 = 2 * q, p1 = 2 * q + 1;
                const ull s00 = add2(gv.x, gri0[p0]);
                const ull s01 = add2(gv.y, gri0[p1]);
                const ull s10 = add2(gv.x, gri1[p0]);
                const ull s11 = add2(gv.y, gri1[p1]);
                a00 = fma2(wv.x, s00 & ABS2, a00);
                a01 = fma2(wv.y, s01 & ABS2, a01);
                a10 = fma2(wv.x, s10 & ABS2, a10);
                a11 = fma2(wv.y, s11 & ABS2, a11);
            }
            float2 pv;
            {
                float lo, hi; unpack2(add2(a00, a01), lo, hi);
                const float p = __expf(slj + Sr0 + lo + hi);
                pv.x = mw0 ? p : 0.f; sum0 += pv.x;
            }
            {
                float lo, hi; unpack2(add2(a10, a11), lo, hi);
                const float p = __expf(slj + Sr1 + lo + hi);
                pv.y = mw1 ? p : 0.f; sum1 += pv.y;
            }
            *(float2*)(at_s + j * ATS + r0) = pv;
        }
#pragma unroll
        for (int o = 16; o; o >>= 1) {
            sum0 += __shfl_xor_sync(0xffffffffu, sum0, o);
            sum1 += __shfl_xor_sync(0xffffffffu, sum1, o);
        }
        if (lane == 0) {
            sinv[r0 + 0] = 1.0f / sum0;
            sinv[r0 + 1] = 1.0f / sum1;
        }
    }
    __syncthreads();

    // ---- pass 2: out partials, i-pair packed ----
    // thread = (fq 0..7, ig 0..3, jq=warp 0..15): 4 f x 8 i x 32 j
    {
        const int fq = tid & 7;
        const int ig = (tid >> 3) & 3;
        const int jq = warp;
        ull acc[4][4] = {};                        // [i-pair][f]
        const int jbeg = jq * 32;
#pragma unroll 4
        for (int jo = 0; jo < 32; jo++) {
            const int j = jbeg + jo;
            const float4 g4 = *(const float4*)(gr_s + j * GRS + fq * 4);
            const ull pg0 = pack2(g4.x, g4.x);
            const ull pg1 = pack2(g4.y, g4.y);
            const ull pg2 = pack2(g4.z, g4.z);
            const ull pg3 = pack2(g4.w, g4.w);
            const ull* ap = (const ull*)(at_s + j * ATS + ig * 8);
#pragma unroll
            for (int p = 0; p < 4; p++) {
                const ull a = ap[p];
                acc[p][0] = fma2(a, pg0, acc[p][0]);
                acc[p][1] = fma2(a, pg1, acc[p][1]);
                acc[p][2] = fma2(a, pg2, acc[p][2]);
                acc[p][3] = fma2(a, pg3, acc[p][3]);
            }
        }
        __syncthreads();                           // gl_s dead -> partials
        ull* part = (ull*)gl_s;                    // [16 jq][16 ipair][32 f]
#pragma unroll
        for (int p = 0; p < 4; p++) {
#pragma unroll
            for (int k = 0; k < 4; k++)
                part[((size_t)jq * 16 + ig * 4 + p) * 32 + fq * 4 + k] = acc[p][k];
        }
    }
    __syncthreads();

    // ---- final reduce over 16 j-partials + scale + store ----
    {
        const int ip = tid >> 5;                   // 0..15 (i-pair)
        const int f  = tid & 31;
        const ull* part = (const ull*)gl_s;
        ull s = 0;
#pragma unroll
        for (int q = 0; q < 16; q++)
            s = add2(s, part[((size_t)q * 16 + ip) * 32 + f]);
        float lo, hi; unpack2(s, lo, hi);
        const int il = ip * 2;
        float* op = out + ((size_t)(b * NN + i0 + il)) * HF + h * NF + f;
        op[0]  = lo * sinv[il];
        op[HF] = hi * sinv[il + 1];
    }
}

// ---------------------------------------------------------------------------
extern "C" void kernel_launch(void* const* d_in, const int* in_sizes, int n_in,
                              void* d_out, int out_size) {
    (void)in_sizes; (void)n_in; (void)out_size;
    const float* h      = (const float*)d_in[0];
    const int*   adj    = (const int*)  d_in[1];
    const float* W_l    = (const float*)d_in[2];
    const float* W_r    = (const float*)d_in[3];
    const float* attn_w = (const float*)d_in[4];
    float* out = (float*)d_out;

    cudaFuncSetAttribute(attn_kernel,
                         cudaFuncAttributeMaxDynamicSharedMemorySize, SMEM_BYTES);

    dim3 gg(8, 32);
    gemm_kernel<<<gg, 256>>>(h, W_l, W_r);

    dim3 ag(NN / ITILE, NH, NB);
    attn_kernel<<<ag, 512, SMEM_BYTES>>>(adj, attn_w, out);
}